// round 2
// baseline (speedup 1.0000x reference)
#include <cuda_runtime.h>
#include <cuda_bf16.h>

// LogSignature depth=4 of path (B=128, T=512, C=8).
// Output per batch: [L1(8) | L2(64) | L3(512) | L4(4096)] = 4680 floats.
//
// One CTA per batch, 512 threads = one per (i,j,k) in {0..7}^3.
// Thread state (registers only):
//   r1 = L1[i]        (replicated across the 64 threads sharing i)
//   r2 = L2[i*8+j]    (replicated across the 8 threads sharing ij)
//   r3 = L3[ijk]      (exclusive)
//   a[0..7] = L4[ijk][0..7] (exclusive)
// Chen step with exp(d) (d = segment increment):
//   g      = r3 + 1/2 r2 dk + 1/6 r1 dj dk + 1/24 di dj dk
//   a[l]  += g * d[l]
//   r3    += r2 dk + 1/2 r1 dj dk + 1/6 di dj dk
//   r2    += r1 dj + 1/2 di dj
//   r1    += di
// No inter-thread communication -> no __syncthreads in the main loop.
//
// log(1+x) truncated at depth 4 collapses to closed form per element:
//   out4[ijkl] = s4 + P*s1[l] + Q*s2[kl] + R*s3[jkl]
//     P = -1/2 s3ijk + 1/3 (si*s2jk + s2ij*sk) - 1/4 si sj sk
//     Q = -1/2 s2ij + 1/3 si sj
//     R = -1/2 si
//   out3[ijk]  = s3 - 1/2 (si*s2jk + s2ij*sk) + 1/3 si sj sk
//   out2[ij]   = s2 - 1/2 si sj
//   out1[i]    = s1

#define BATCH 128
#define TLEN  512
#define CH    8
#define NSTEP (TLEN - 1)      // 511
#define OUT_STRIDE 4680       // 8 + 64 + 512 + 4096
#define OFF_L2 8
#define OFF_L3 72
#define OFF_L4 584

__global__ void __launch_bounds__(512, 1)
logsig_kernel(const float* __restrict__ path, float* __restrict__ out)
{
    __shared__ __align__(16) float s_dx[NSTEP * CH];  // 16352 B
    __shared__ __align__(16) float s1[8];
    __shared__ __align__(16) float s2[64];
    __shared__ __align__(16) float s3[512];

    const int b   = blockIdx.x;
    const int tid = threadIdx.x;
    const float* p = path + (size_t)b * TLEN * CH;

    // Precompute increments into shared (coalesced global loads).
    for (int idx = tid; idx < NSTEP * CH; idx += 512)
        s_dx[idx] = p[idx + CH] - p[idx];
    __syncthreads();

    const int i = tid >> 6;
    const int j = (tid >> 3) & 7;
    const int k = tid & 7;

    float r1 = 0.f, r2 = 0.f, r3 = 0.f;
    float a0 = 0.f, a1 = 0.f, a2 = 0.f, a3 = 0.f;
    float a4 = 0.f, a5 = 0.f, a6 = 0.f, a7 = 0.f;

    const float C2 = 0.5f;
    const float C3 = 1.0f / 6.0f;
    const float C4 = 1.0f / 24.0f;

    #pragma unroll 4
    for (int t = 0; t < NSTEP; ++t) {
        const float* d = &s_dx[t * CH];
        const float4 dlo = *(const float4*)(d);       // broadcast LDS.128
        const float4 dhi = *(const float4*)(d + 4);   // broadcast LDS.128
        const float di = d[i];                        // broadcast-class scalar LDS
        const float dj = d[j];
        const float dk = d[k];

        const float djk  = dj * dk;
        const float dijk = di * djk;
        const float u = r2 * dk;     // uses OLD r2
        const float v = r1 * djk;    // uses OLD r1

        // level-4 rank-1 update
        float g = r3;
        g = fmaf(C2, u, g);
        g = fmaf(C3, v, g);
        g = fmaf(C4, dijk, g);
        a0 = fmaf(g, dlo.x, a0);
        a1 = fmaf(g, dlo.y, a1);
        a2 = fmaf(g, dlo.z, a2);
        a3 = fmaf(g, dlo.w, a3);
        a4 = fmaf(g, dhi.x, a4);
        a5 = fmaf(g, dhi.y, a5);
        a6 = fmaf(g, dhi.z, a6);
        a7 = fmaf(g, dhi.w, a7);

        // level-3 update (old r2, r1 via u, v)
        float t3 = r3 + u;
        t3 = fmaf(C2, v, t3);
        t3 = fmaf(C3, dijk, t3);
        r3 = t3;

        // level-2 update (old r1)
        float t2 = fmaf(r1, dj, r2);
        t2 = fmaf(C2 * di, dj, t2);
        r2 = t2;

        // level-1
        r1 += di;
    }

    // Publish final signature levels needed cross-thread.
    s3[tid] = r3;
    if (k == 0)        s2[i * 8 + j] = r2;
    if ((tid & 63) == 0) s1[i] = r1;
    __syncthreads();

    const float si = s1[i];
    const float sj = s1[j];
    const float sk = s1[k];
    const float s2ij = r2;             // own replicated copy == s2[i*8+j]
    const float s2jk = s2[j * 8 + k];
    const float s3ijk = r3;

    const float cross = fmaf(si, s2jk, s2ij * sk);  // si*s2jk + s2ij*sk
    const float sss   = si * sj * sk;

    const float P = fmaf(1.0f / 3.0f, cross, -0.5f * s3ijk) - 0.25f * sss;
    const float Q = fmaf(1.0f / 3.0f, si * sj, -0.5f * s2ij);
    const float R = -0.5f * si;

    const float4 s1lo = *(const float4*)(s1);
    const float4 s1hi = *(const float4*)(s1 + 4);
    const float4 s2lo = *(const float4*)(&s2[k * 8]);
    const float4 s2hi = *(const float4*)(&s2[k * 8 + 4]);
    const float4 s3lo = *(const float4*)(&s3[j * 64 + k * 8]);
    const float4 s3hi = *(const float4*)(&s3[j * 64 + k * 8 + 4]);

    float4 w0, w1;
    w0.x = a0 + P * s1lo.x + Q * s2lo.x + R * s3lo.x;
    w0.y = a1 + P * s1lo.y + Q * s2lo.y + R * s3lo.y;
    w0.z = a2 + P * s1lo.z + Q * s2lo.z + R * s3lo.z;
    w0.w = a3 + P * s1lo.w + Q * s2lo.w + R * s3lo.w;
    w1.x = a4 + P * s1hi.x + Q * s2hi.x + R * s3hi.x;
    w1.y = a5 + P * s1hi.y + Q * s2hi.y + R * s3hi.y;
    w1.z = a6 + P * s1hi.z + Q * s2hi.z + R * s3hi.z;
    w1.w = a7 + P * s1hi.w + Q * s2hi.w + R * s3hi.w;

    float* ob = out + (size_t)b * OUT_STRIDE;

    // L4: 16B-aligned vector stores
    *(float4*)(&ob[OFF_L4 + tid * 8])     = w0;
    *(float4*)(&ob[OFF_L4 + tid * 8 + 4]) = w1;

    // L3
    const float o3 = fmaf(1.0f / 3.0f, sss, fmaf(-0.5f, cross, s3ijk));
    ob[OFF_L3 + tid] = o3;

    // L2 (one writer per (i,j))
    if (k == 0)
        ob[OFF_L2 + i * 8 + j] = fmaf(-0.5f * si, sj, r2);

    // L1 (one writer per i)
    if ((tid & 63) == 0)
        ob[i] = r1;
}

extern "C" void kernel_launch(void* const* d_in, const int* in_sizes, int n_in,
                              void* d_out, int out_size)
{
    const float* path = (const float*)d_in[0];
    float* out = (float*)d_out;
    logsig_kernel<<<BATCH, 512>>>(path, out);
}

// round 3
// speedup vs baseline: 1.2761x; 1.2761x over previous
#include <cuda_runtime.h>
#include <cuda_bf16.h>

// LogSignature depth=4 of path (B=128, T=512, C=8).
// Output per batch: [L1(8) | L2(64) | L3(512) | L4(4096)] = 4680 floats.
//
// One CTA per batch, 512 threads = one per (i,j,k) in {0..7}^3.
// NEW: the two f32 lanes of Blackwell packed f32x2 ops carry the TWO TIME
// HALVES of the batch: lane-lo = Chen scan over steps [0,256), lane-hi =
// steps [256,511) (padded with one zero increment = identity). Increments
// are stored pre-interleaved in shared so every LDS delivers packed
// operands directly. After the loop the two half-signatures A,B are
// combined with one truncated tensor product S = A (x) B, then log(S) in
// closed form.

#define BATCH 128
#define TLEN  512
#define CH    8
#define NHALF 256             // packed steps per CTA
#define OUT_STRIDE 4680       // 8 + 64 + 512 + 4096
#define OFF_L2 8
#define OFF_L3 72
#define OFF_L4 584

typedef unsigned long long u64;

__device__ __forceinline__ u64 ffma2(u64 a, u64 b, u64 c) {
    u64 d; asm("fma.rn.f32x2 %0, %1, %2, %3;" : "=l"(d) : "l"(a), "l"(b), "l"(c)); return d;
}
__device__ __forceinline__ u64 fmul2(u64 a, u64 b) {
    u64 d; asm("mul.rn.f32x2 %0, %1, %2;" : "=l"(d) : "l"(a), "l"(b)); return d;
}
__device__ __forceinline__ u64 fadd2(u64 a, u64 b) {
    u64 d; asm("add.rn.f32x2 %0, %1, %2;" : "=l"(d) : "l"(a), "l"(b)); return d;
}
__device__ __forceinline__ u64 pack2(float x, float y) {
    u64 d; asm("mov.b64 %0, {%1, %2};" : "=l"(d) : "f"(x), "f"(y)); return d;
}
__device__ __forceinline__ void unpack2(u64 a, float& x, float& y) {
    asm("mov.b64 {%0, %1}, %2;" : "=f"(x), "=f"(y) : "l"(a));
}

// packed constants (both lanes equal): bit patterns of 0.5f, 1/6f, 1/24f
#define C2P 0x3F0000003F000000ULL
#define C3P 0x3E2AAAAB3E2AAAABULL
#define C4P 0x3D2AAAAB3D2AAAABULL

__global__ void __launch_bounds__(512, 1)
logsig_kernel(const float* __restrict__ path, float* __restrict__ out)
{
    __shared__ __align__(16) u64 s_dx2[NHALF * CH];   // 16 KB, float2-interleaved
    __shared__ float sB1[8],  sB2[64],  sB3[512];     // second-half signature
    __shared__ float sc1[8],  sc2[64],  sc3[512];     // combined signature

    const int b   = blockIdx.x;
    const int tid = threadIdx.x;
    const float* p = path + (size_t)b * TLEN * CH;

    // Build interleaved increments: s_dx2[t][c] = (dx[t][c], dx[256+t][c] or 0)
    for (int idx = tid; idx < NHALF * CH; idx += 512) {
        const int t = idx >> 3;           // 0..255
        const float dxA = p[idx + CH] - p[idx];
        float dxB = 0.0f;
        if (t < NHALF - 1)                // second-half step 256+t valid for t<255
            dxB = p[idx + (NHALF + 1) * CH] - p[idx + NHALF * CH];
        s_dx2[idx] = pack2(dxA, dxB);
    }
    __syncthreads();

    const int i = tid >> 6;
    const int j = (tid >> 3) & 7;
    const int k = tid & 7;

    u64 r1 = 0, r2 = 0, r3 = 0;
    u64 a0 = 0, a1 = 0, a2 = 0, a3 = 0, a4 = 0, a5 = 0, a6 = 0, a7 = 0;

    const u64 c2 = C2P, c3 = C3P, c4 = C4P;

    #pragma unroll 4
    for (int t = 0; t < NHALF; ++t) {
        const u64* d = &s_dx2[t * CH];
        const ulonglong2 q0 = *(const ulonglong2*)(d + 0);   // ch 0,1 (packed halves)
        const ulonglong2 q1 = *(const ulonglong2*)(d + 2);   // ch 2,3
        const ulonglong2 q2 = *(const ulonglong2*)(d + 4);   // ch 4,5
        const ulonglong2 q3 = *(const ulonglong2*)(d + 6);   // ch 6,7
        const u64 di = d[i];
        const u64 dj = d[j];
        const u64 dk = d[k];

        const u64 djk  = fmul2(dj, dk);
        const u64 dijk = fmul2(di, djk);
        const u64 u = fmul2(r2, dk);     // OLD r2
        const u64 v = fmul2(r1, djk);    // OLD r1

        // level-4 rank-1 update: a[l] += g * d[l]
        u64 g = ffma2(c2, u, r3);
        g = ffma2(c3, v, g);
        g = ffma2(c4, dijk, g);
        a0 = ffma2(g, q0.x, a0);
        a1 = ffma2(g, q0.y, a1);
        a2 = ffma2(g, q1.x, a2);
        a3 = ffma2(g, q1.y, a3);
        a4 = ffma2(g, q2.x, a4);
        a5 = ffma2(g, q2.y, a5);
        a6 = ffma2(g, q3.x, a6);
        a7 = ffma2(g, q3.y, a7);

        // level-3
        r3 = fadd2(r3, u);
        r3 = ffma2(c2, v, r3);
        r3 = ffma2(c3, dijk, r3);

        // level-2: r2 += dj * (r1 + 0.5*di)
        const u64 tmp = ffma2(c2, di, r1);
        r2 = ffma2(dj, tmp, r2);

        // level-1
        r1 = fadd2(r1, di);
    }

    // ---- unpack half-signatures: A = lane lo (steps 0..255), B = lane hi ----
    float A1, B1, A2, B2, A3, B3;
    unpack2(r1, A1, B1);
    unpack2(r2, A2, B2);
    unpack2(r3, A3, B3);
    float aA[8], aB[8];
    unpack2(a0, aA[0], aB[0]); unpack2(a1, aA[1], aB[1]);
    unpack2(a2, aA[2], aB[2]); unpack2(a3, aA[3], aB[3]);
    unpack2(a4, aA[4], aB[4]); unpack2(a5, aA[5], aB[5]);
    unpack2(a6, aA[6], aB[6]); unpack2(a7, aA[7], aB[7]);

    // publish B levels needed cross-thread
    sB3[tid] = B3;
    if (k == 0)          sB2[i * 8 + j] = B2;
    if ((tid & 63) == 0) sB1[i] = B1;
    __syncthreads();

    // ---- Chen combine: S = A (x) B ----
    const float c1v = A1 + B1;                                        // replicated per i
    const float c2v = A2 + B2 + A1 * sB1[j];                          // replicated per ij
    const float c3v = A3 + B3 + A1 * sB2[j * 8 + k] + A2 * sB1[k];    // own ijk

    float w[8];
    {
        const float* b3row = &sB3[(j * 8 + k) * 8];
        const float* b2row = &sB2[k * 8];
        #pragma unroll
        for (int l = 0; l < 8; ++l) {
            float t4 = aA[l] + aB[l];
            t4 = fmaf(A3, sB1[l], t4);
            t4 = fmaf(A2, b2row[l], t4);
            t4 = fmaf(A1, b3row[l], t4);
            w[l] = t4;
        }
    }

    // publish combined levels for the log tail
    sc3[tid] = c3v;
    if (k == 0)          sc2[i * 8 + j] = c2v;
    if ((tid & 63) == 0) sc1[i] = c1v;
    __syncthreads();

    // ---- closed-form log(1+x) truncated at depth 4 ----
    const float si = sc1[i];
    const float sj = sc1[j];
    const float sk = sc1[k];
    const float s2ij  = c2v;
    const float s2jk  = sc2[j * 8 + k];
    const float s3ijk = c3v;

    const float cross = fmaf(si, s2jk, s2ij * sk);
    const float sss   = si * sj * sk;

    const float P = fmaf(1.0f / 3.0f, cross, -0.5f * s3ijk) - 0.25f * sss;
    const float Q = fmaf(1.0f / 3.0f, si * sj, -0.5f * s2ij);
    const float R = -0.5f * si;

    float* ob = out + (size_t)b * OUT_STRIDE;

    {
        const float* s3row = &sc3[(j * 8 + k) * 8];
        const float* s2row = &sc2[k * 8];
        float4 w0, w1;
        w0.x = w[0] + P * sc1[0] + Q * s2row[0] + R * s3row[0];
        w0.y = w[1] + P * sc1[1] + Q * s2row[1] + R * s3row[1];
        w0.z = w[2] + P * sc1[2] + Q * s2row[2] + R * s3row[2];
        w0.w = w[3] + P * sc1[3] + Q * s2row[3] + R * s3row[3];
        w1.x = w[4] + P * sc1[4] + Q * s2row[4] + R * s3row[4];
        w1.y = w[5] + P * sc1[5] + Q * s2row[5] + R * s3row[5];
        w1.z = w[6] + P * sc1[6] + Q * s2row[6] + R * s3row[6];
        w1.w = w[7] + P * sc1[7] + Q * s2row[7] + R * s3row[7];
        *(float4*)(&ob[OFF_L4 + tid * 8])     = w0;
        *(float4*)(&ob[OFF_L4 + tid * 8 + 4]) = w1;
    }

    // L3
    ob[OFF_L3 + tid] = fmaf(1.0f / 3.0f, sss, fmaf(-0.5f, cross, s3ijk));

    // L2 (one writer per (i,j))
    if (k == 0)
        ob[OFF_L2 + i * 8 + j] = fmaf(-0.5f * si, sj, c2v);

    // L1 (one writer per i)
    if ((tid & 63) == 0)
        ob[i] = c1v;
}

extern "C" void kernel_launch(void* const* d_in, const int* in_sizes, int n_in,
                              void* d_out, int out_size)
{
    const float* path = (const float*)d_in[0];
    float* out = (float*)d_out;
    logsig_kernel<<<BATCH, 512>>>(path, out);
}